// round 5
// baseline (speedup 1.0000x reference)
#include <cuda_runtime.h>
#include <cuda_bf16.h>
#include <cstdint>

#define ALPHA 0.2f
#define KDIM 4096
#define NDIM 1024
#define CH 16
#define NCHUNK (KDIM / CH)   // 256

// ---------------- scratch (__device__ globals; no allocs allowed) ----------
__device__ float g_s1[KDIM], g_s2[KDIM];
__device__ float g_ea[KDIM], g_ec[KDIM];        // exp(s1), exp(0.2 s1)
__device__ float g_eb[KDIM], g_ed[KDIM];        // exp(s2), exp(0.2 s2)
__device__ float g_sorted[KDIM];                // s2 ascending
__device__ int   g_sigma[KDIM];                 // sorted rank -> original index
__device__ float g_ebS[KDIM], g_edS[KDIM];      // eb/ed in sorted order
__device__ float g_sb[KDIM + 1], g_sd[KDIM + 1];// scalar global suffix sums
__device__ float g_sufB[(size_t)KDIM * NDIM];   // chunk-local vector suffix sums (16MB)
__device__ float g_sufD[(size_t)KDIM * NDIM];   // 16MB
__device__ float g_carB[NCHUNK * NDIM];         // chunk carries (exclusive suffix of totals)
__device__ float g_carD[NCHUNK * NDIM];

// ---------------------------------------------------------------------------
// K1: s1[i] = x[i,:].w1 ; s2[i] = x[i,:].w2 ; plus the 4 exp factors
// ---------------------------------------------------------------------------
__global__ void k_scores(const float* __restrict__ x, const float* __restrict__ w) {
    int i = blockIdx.x;
    int t = threadIdx.x;  // 256 threads * float4 = 1024
    const float4* xr = reinterpret_cast<const float4*>(x + (size_t)i * NDIM);
    const float4* w1 = reinterpret_cast<const float4*>(w);
    const float4* w2 = reinterpret_cast<const float4*>(w + NDIM);
    float4 xv = xr[t];
    float4 a = w1[t];
    float4 b = w2[t];
    float d1 = xv.x * a.x + xv.y * a.y + xv.z * a.z + xv.w * a.w;
    float d2 = xv.x * b.x + xv.y * b.y + xv.z * b.z + xv.w * b.w;
    #pragma unroll
    for (int o = 16; o > 0; o >>= 1) {
        d1 += __shfl_down_sync(0xffffffffu, d1, o);
        d2 += __shfl_down_sync(0xffffffffu, d2, o);
    }
    __shared__ float sm1[8], sm2[8];
    if ((t & 31) == 0) { sm1[t >> 5] = d1; sm2[t >> 5] = d2; }
    __syncthreads();
    if (t == 0) {
        float s1 = 0.f, s2 = 0.f;
        #pragma unroll
        for (int q = 0; q < 8; q++) { s1 += sm1[q]; s2 += sm2[q]; }
        g_s1[i] = s1;
        g_s2[i] = s2;
        g_ea[i] = __expf(s1);
        g_ec[i] = __expf(ALPHA * s1);
        g_eb[i] = __expf(s2);
        g_ed[i] = __expf(ALPHA * s2);
    }
}

// ---------------------------------------------------------------------------
// K2: exact rank of each s2 (ties broken by index) -> sorted arrays (scatter)
// ---------------------------------------------------------------------------
__global__ void k_rank() {
    int i = blockIdx.x;
    int t = threadIdx.x;  // 256
    float v = g_s2[i];
    int cnt = 0;
    #pragma unroll 4
    for (int j = t; j < KDIM; j += 256) {
        float u = g_s2[j];
        cnt += (u < v) || (u == v && j < i);
    }
    #pragma unroll
    for (int o = 16; o > 0; o >>= 1) cnt += __shfl_down_sync(0xffffffffu, cnt, o);
    __shared__ int sm[8];
    if ((t & 31) == 0) sm[t >> 5] = cnt;
    __syncthreads();
    if (t == 0) {
        int r = 0;
        #pragma unroll
        for (int q = 0; q < 8; q++) r += sm[q];
        g_sorted[r] = v;
        g_sigma[r] = i;
        g_ebS[r] = g_eb[i];
        g_edS[r] = g_ed[i];
    }
}

// ---------------------------------------------------------------------------
// K3: scalar global suffix sums of ebS and edS (one block, 1024 threads)
// ---------------------------------------------------------------------------
__global__ void k_sscan() {
    __shared__ float p[1024];
    int t = threadIdx.x;
    #pragma unroll
    for (int pass = 0; pass < 2; pass++) {
        const float* src = pass ? g_edS : g_ebS;
        float* dst = pass ? g_sd : g_sb;
        float e0 = src[4 * t], e1 = src[4 * t + 1], e2 = src[4 * t + 2], e3 = src[4 * t + 3];
        float part = e0 + e1 + e2 + e3;
        float v = part;
        p[t] = v;
        __syncthreads();
        #pragma unroll
        for (int off = 1; off < 1024; off <<= 1) {
            float add = (t + off < 1024) ? p[t + off] : 0.f;
            __syncthreads();
            v += add;
            p[t] = v;
            __syncthreads();
        }
        float excl = (t < 1023) ? p[t + 1] : 0.f;
        float s3 = e3 + excl;
        float s2v = e2 + s3;
        float s1v = e1 + s2v;
        float s0 = e0 + s1v;
        dst[4 * t]     = s0;
        dst[4 * t + 1] = s1v;
        dst[4 * t + 2] = s2v;
        dst[4 * t + 3] = s3;
        if (t == 0) dst[KDIM] = 0.f;
        __syncthreads();
    }
}

// ---------------------------------------------------------------------------
// K4: chunk-local vector suffix sums. Block = one chunk of CH=16 sorted rows,
// 1024 columns (256 threads x float4). All 16 gathered rows loaded up-front
// into registers (MLP=16), then a pure-register FMA suffix chain + stores.
// ---------------------------------------------------------------------------
__global__ __launch_bounds__(256, 2) void k_scan(const float* __restrict__ x) {
    int c = blockIdx.x;
    int tid = threadIdx.x;
    int col = tid * 4;
    __shared__ int ssig[CH];
    __shared__ float scb[CH], scd[CH];
    if (tid < CH) {
        int k = c * CH + tid;
        ssig[tid] = g_sigma[k];
        scb[tid] = g_ebS[k];
        scd[tid] = g_edS[k];
    }
    __syncthreads();

    // Load all CH rows (independent -> full MLP)
    float4 y[CH];
    #pragma unroll
    for (int r = 0; r < CH; r++)
        y[r] = __ldg(reinterpret_cast<const float4*>(x + (size_t)ssig[r] * NDIM + col));

    float4 aB = make_float4(0.f, 0.f, 0.f, 0.f);
    float4 aD = make_float4(0.f, 0.f, 0.f, 0.f);

    #pragma unroll
    for (int r = CH - 1; r >= 0; r--) {
        float cb = scb[r], cd = scd[r];
        aB.x = fmaf(cb, y[r].x, aB.x); aB.y = fmaf(cb, y[r].y, aB.y);
        aB.z = fmaf(cb, y[r].z, aB.z); aB.w = fmaf(cb, y[r].w, aB.w);
        aD.x = fmaf(cd, y[r].x, aD.x); aD.y = fmaf(cd, y[r].y, aD.y);
        aD.z = fmaf(cd, y[r].z, aD.z); aD.w = fmaf(cd, y[r].w, aD.w);
        size_t ro = (size_t)(c * CH + r) * NDIM + col;
        *reinterpret_cast<float4*>(g_sufB + ro) = aB;
        *reinterpret_cast<float4*>(g_sufD + ro) = aD;
    }
}

// ---------------------------------------------------------------------------
// K5: chunk carries — exclusive suffix sums of chunk totals per column.
// 4 blocks x 256 threads; one column per thread; groups of 16 chunk totals
// preloaded for MLP.
// ---------------------------------------------------------------------------
__global__ __launch_bounds__(256) void k_carry() {
    int col = blockIdx.x * 256 + threadIdx.x;
    float aB = 0.f, aD = 0.f;
    for (int g = NCHUNK / 16 - 1; g >= 0; g--) {
        float tB[16], tD[16];
        #pragma unroll
        for (int q = 0; q < 16; q++) {
            size_t ro = (size_t)((g * 16 + q) * CH) * NDIM + col;
            tB[q] = g_sufB[ro];
            tD[q] = g_sufD[ro];
        }
        #pragma unroll
        for (int q = 15; q >= 0; q--) {
            int c = g * 16 + q;
            g_carB[c * NDIM + col] = aB;
            g_carD[c * NDIM + col] = aD;
            aB += tB[q];
            aD += tD[q];
        }
    }
}

// ---------------------------------------------------------------------------
// K6: output. Block = row i. Binary-search rank t_i of -s1_i, form
// h_i = (a_i*SufB(t) + c_i*(TotD - SufD(t))) / Z_i  with Z from scalar tables.
// ---------------------------------------------------------------------------
__global__ __launch_bounds__(256) void k_out(float* __restrict__ out) {
    int i = blockIdx.x;
    int tid = threadIdx.x;
    __shared__ int sT;
    __shared__ float sAZ, sCZ;
    if (tid == 0) {
        float key = -g_s1[i];
        int lo = 0, hi = KDIM;
        while (lo < hi) {
            int mid = (lo + hi) >> 1;
            if (g_sorted[mid] <= key) lo = mid + 1;
            else hi = mid;
        }
        int t = lo;
        float a = g_ea[i], c = g_ec[i];
        float Z = a * g_sb[t] + c * (g_sd[0] - g_sd[t]);
        float rZ = 1.f / Z;
        sT = t;
        sAZ = a * rZ;
        sCZ = c * rZ;
    }
    __syncthreads();
    int t = sT;
    float aZ = sAZ, cZ = sCZ;
    int col = tid * 4;

    bool in = (t < KDIM);
    int tt = in ? t : 0;
    int ch = tt / CH;
    size_t ro = (size_t)tt * NDIM + col;
    size_t co = (size_t)ch * NDIM + col;

    float4 sB = *reinterpret_cast<const float4*>(g_sufB + ro);
    float4 cB = *reinterpret_cast<const float4*>(g_carB + co);
    float4 sD = *reinterpret_cast<const float4*>(g_sufD + ro);
    float4 cD = *reinterpret_cast<const float4*>(g_carD + co);
    float4 sD0 = *reinterpret_cast<const float4*>(g_sufD + col);
    float4 cD0 = *reinterpret_cast<const float4*>(g_carD + col);

    float m = in ? 1.f : 0.f;  // t == KDIM: positive part empty, neg = full total
    float4 h;
    h.x = aZ * m * (sB.x + cB.x) + cZ * ((sD0.x + cD0.x) - m * (sD.x + cD.x));
    h.y = aZ * m * (sB.y + cB.y) + cZ * ((sD0.y + cD0.y) - m * (sD.y + cD.y));
    h.z = aZ * m * (sB.z + cB.z) + cZ * ((sD0.z + cD0.z) - m * (sD.z + cD.z));
    h.w = aZ * m * (sB.w + cB.w) + cZ * ((sD0.w + cD0.w) - m * (sD.w + cD.w));

    *reinterpret_cast<float4*>(out + (size_t)i * NDIM + col) = h;
}

// ---------------------------------------------------------------------------
extern "C" void kernel_launch(void* const* d_in, const int* in_sizes, int n_in,
                              void* d_out, int out_size) {
    const float* x = (const float*)d_in[0];   // (4096, 1024) fp32
    const float* w = (const float*)d_in[1];   // (2048, 1) fp32
    float* out = (float*)d_out;               // (4096, 1024) fp32

    k_scores<<<KDIM, 256>>>(x, w);
    k_rank<<<KDIM, 256>>>();
    k_sscan<<<1, 1024>>>();
    k_scan<<<NCHUNK, 256>>>(x);
    k_carry<<<4, 256>>>();
    k_out<<<KDIM, 256>>>(out);
}